// round 7
// baseline (speedup 1.0000x reference)
#include <cuda_runtime.h>
#include <cuda_fp16.h>
#include <cstdint>

// ============================================================================
// z_{k+1} = tanh(z_k @ W^T + b + x), 25 fixed iterations (conv check can't fire).
// Transposed formulation: D[feat, batch] = W[feat, k] @ z^T[k, batch].
//   - A = W lives in REGISTERS (128 regs/thread, loaded once via ldmatrix)
//     -> zero W smem traffic in steady state (was 1 MB/CTA/iter, the binder).
//   - B = z in SMEM, batch-major 512B rows, XOR-swizzled (identical layout +
//     ldmatrix addressing to the validated R5 W path), double-buffered,
//     ONE __syncthreads per iteration.
//   - xT[f][b] = x[b][f] + b[f] precomputed (fp32, __device__ buffer) so the
//     feature-major epilogue loads are coalesced and bias is folded in.
//   - iteration 0 skips the GEMM (z0 = 0).
// ============================================================================

#define NT     256
#define NB     256          // CTAs, 128 batch rows each
#define ITERS  25
#define BATCH  32768
#define F      256
#define ZBUF_BYTES 65536    // 128 rows x 512B
#define SMEM_TOTAL (2 * ZBUF_BYTES)   // also reused as 128KB W staging

__device__ float g_xT[(size_t)F * BATCH];   // 32 MB scratch (sanctioned)

__device__ __forceinline__ uint32_t smem_u32(const void* p) {
    uint32_t a;
    asm("{ .reg .u64 t; cvta.to.shared.u64 t, %1; cvt.u32.u64 %0, t; }"
        : "=r"(a) : "l"(p));
    return a;
}

__device__ __forceinline__ float tanh_fast(float u) {
    float e, r;
    asm("ex2.approx.f32 %0, %1;" : "=f"(e) : "f"(u * 2.885390081777927f));
    asm("rcp.approx.f32 %0, %1;" : "=f"(r) : "f"(e + 1.0f));
    return fmaf(-2.0f, r, 1.0f);
}

__device__ __forceinline__ void mma16816(float* d, const uint32_t* a,
                                         uint32_t b0, uint32_t b1) {
    asm volatile(
        "mma.sync.aligned.m16n8k16.row.col.f32.f16.f16.f32 "
        "{%0,%1,%2,%3}, {%4,%5,%6,%7}, {%8,%9}, {%0,%1,%2,%3};"
        : "+f"(d[0]), "+f"(d[1]), "+f"(d[2]), "+f"(d[3])
        : "r"(a[0]), "r"(a[1]), "r"(a[2]), "r"(a[3]), "r"(b0), "r"(b1));
}

__device__ __forceinline__ void ldsm4(uint32_t* r, uint32_t addr) {
    asm volatile("ldmatrix.sync.aligned.m8n8.x4.shared.b16 {%0,%1,%2,%3}, [%4];"
                 : "=r"(r[0]), "=r"(r[1]), "=r"(r[2]), "=r"(r[3]) : "r"(addr));
}

__device__ __forceinline__ void sts16(uint32_t addr, float v) {
    const unsigned short h = __half_as_ushort(__float2half_rn(v));
    asm volatile("st.shared.u16 [%0], %1;" :: "r"(addr), "h"(h) : "memory");
}

// ---- setup: xT[f][b] = x[b][f] + bias[f] -----------------------------------
__global__ void xt_kernel(const float* __restrict__ x, const float* __restrict__ b) {
    __shared__ float tile[32][33];
    const int bb = blockIdx.x * 32, fb = blockIdx.y * 32;
    const int tx = threadIdx.x, ty = threadIdx.y;        // 32 x 8
    #pragma unroll
    for (int i = 0; i < 32; i += 8)
        tile[ty + i][tx] = x[(size_t)(bb + ty + i) * F + fb + tx];
    __syncthreads();
    #pragma unroll
    for (int i = 0; i < 32; i += 8) {
        const int f = fb + ty + i;
        g_xT[(size_t)f * BATCH + bb + tx] = tile[tx][ty + i] + b[f];
    }
}

// ---- main persistent kernel -------------------------------------------------
__global__ void __launch_bounds__(NT, 1)
fp_kernel(float* __restrict__ out, const float* __restrict__ W) {
    extern __shared__ char smem[];
    const uint32_t sS = smem_u32(smem);
    const int tid = threadIdx.x, lane = tid & 31, warp = tid >> 5;
    const int g = lane >> 2, tig = lane & 3;

    // ---- stage W fp16 swizzled (rows = feat_out, 512B), then -> A regs ------
    {
        const float2* W2 = reinterpret_cast<const float2*>(W);
        for (int idx = tid; idx < F * (F / 2); idx += NT) {
            const int n = idx >> 7;
            const float2 w = W2[idx];
            uint32_t off = (uint32_t)(n * 512 + (idx & 127) * 4);
            off ^= (uint32_t)((n & 7) << 4);
            *reinterpret_cast<__half2*>(smem + off) = __floats2half2_rn(w.x, w.y);
        }
    }
    __syncthreads();

    const uint32_t xorv = (uint32_t)((lane & 7) << 4);
    uint32_t a[128];                     // W fragments: [mt 2][c 16][r 4]
    {
        // A lane groups: 0-7 m0-7/klo, 8-15 m8-15/klo, 16-23 m0-7/khi, 24-31 m8-15/khi
        const int m_lane = (lane & 7) | (((lane >> 3) & 1) << 3);
        const uint32_t k_seg = (uint32_t)(((lane >> 4) & 1) * 16);
        const int wfeat = warp * 32;
        #pragma unroll
        for (int mt = 0; mt < 2; ++mt)
            #pragma unroll
            for (int c = 0; c < 16; ++c) {
                const uint32_t addr = sS
                    + (uint32_t)((wfeat + mt * 16 + m_lane) * 512)
                    + (((uint32_t)(c * 32) + k_seg) ^ xorv);
                ldsm4(&a[(mt * 16 + c) * 4], addr);
            }
    }
    __syncthreads();                     // staging area now reusable as zbuf

    // B (z) ldmatrix lane groups: 0-7 n0-7/klo, 8-15 n0-7/khi, 16-23 n8-15/klo, ...
    const int n_lane = (lane & 7) + ((lane >> 4) << 3);
    const uint32_t lane_k = (uint32_t)(((lane >> 3) & 1) * 16);
    const int bb_cta = blockIdx.x * 128;            // CTA's batch base
    const int fg0 = warp * 32 + g;                  // thread's feat rows: fg0, +8 (+16 for mt=1)

    #pragma unroll 1
    for (int it = 0; it < ITERS; ++it) {
        const uint32_t zw = sS + (uint32_t)((it & 1) * ZBUF_BYTES);
        const uint32_t zr = sS + (uint32_t)(((it & 1) ^ 1) * ZBUF_BYTES);
        const bool last = (it == ITERS - 1);

        #pragma unroll
        for (int nc = 0; nc < 4; ++nc) {            // batch chunks of 32
            float d[32];
            #pragma unroll
            for (int i = 0; i < 32; ++i) d[i] = 0.0f;

            if (it) {
                const uint32_t rbase = zr + (uint32_t)((nc * 32 + n_lane) * 512);
                #pragma unroll
                for (int c = 0; c < 16; ++c) {
                    uint32_t bf[8];
                    #pragma unroll
                    for (int ntp = 0; ntp < 2; ++ntp)
                        ldsm4(&bf[ntp * 4],
                              rbase + (uint32_t)(ntp * 16 * 512)
                                    + ((lane_k + (uint32_t)(c * 32)) ^ xorv));
                    #pragma unroll
                    for (int mt = 0; mt < 2; ++mt)
                        #pragma unroll
                        for (int nt = 0; nt < 4; ++nt) {
                            const int bi = (nt >> 1) * 4 + (nt & 1) * 2;
                            mma16816(&d[(mt * 4 + nt) * 4],
                                     &a[(mt * 16 + c) * 4], bf[bi], bf[bi + 1]);
                        }
                }
            }

            // ---- epilogue: u = D + xT; z_new = tanh(u) ----------------------
            #pragma unroll
            for (int mt = 0; mt < 2; ++mt)
                #pragma unroll
                for (int nt = 0; nt < 4; ++nt) {
                    const int fg = fg0 + mt * 16;                 // feat rows fg, fg+8
                    const int bl = nc * 32 + nt * 8 + tig * 2;    // batch local
                    const int bglob = bb_cta + bl;
                    const float* dd = &d[(mt * 4 + nt) * 4];
                    const float2 xa = *reinterpret_cast<const float2*>(
                        g_xT + (size_t)fg * BATCH + bglob);
                    const float2 xb = *reinterpret_cast<const float2*>(
                        g_xT + (size_t)(fg + 8) * BATCH + bglob);
                    const float t0 = tanh_fast(dd[0] + xa.x);
                    const float t1 = tanh_fast(dd[1] + xa.y);
                    const float t2 = tanh_fast(dd[2] + xb.x);
                    const float t3 = tanh_fast(dd[3] + xb.y);
                    if (!last) {
                        const uint32_t r0 = zw + (uint32_t)(bl * 512)
                            + (((uint32_t)(fg * 2)) ^ (uint32_t)((bl & 7) << 4));
                        const uint32_t r1 = zw + (uint32_t)((bl + 1) * 512)
                            + (((uint32_t)(fg * 2)) ^ (uint32_t)(((bl + 1) & 7) << 4));
                        sts16(r0, t0);
                        sts16(r1, t1);
                        sts16(r0 ^ 16u, t2);   // feat+8 -> +16B, inside swizzle granule flip
                        sts16(r1 ^ 16u, t3);
                    } else {
                        out[(size_t)bglob * F + fg]           = t0;
                        out[(size_t)(bglob + 1) * F + fg]     = t1;
                        out[(size_t)bglob * F + fg + 8]       = t2;
                        out[(size_t)(bglob + 1) * F + fg + 8] = t3;
                    }
                }
        }
        __syncthreads();   // writes to zw visible; frees zr for next-iter writes
    }
}

// ----------------------------------------------------------------------------
extern "C" void kernel_launch(void* const* d_in, const int* in_sizes, int n_in,
                              void* d_out, int out_size) {
    const float* x = nullptr;
    const float* W = nullptr;
    const float* b = nullptr;
    for (int i = 0; i < n_in; ++i) {
        if (in_sizes[i] == BATCH * F)   x = (const float*)d_in[i];
        else if (in_sizes[i] == F * F)  W = (const float*)d_in[i];
        else if (in_sizes[i] == F)      b = (const float*)d_in[i];
    }
    if (!x && n_in > 0) x = (const float*)d_in[0];
    if (!W && n_in > 1) W = (const float*)d_in[1];
    if (!b && n_in > 2) b = (const float*)d_in[2];

    static int once = 0;
    if (!once) {
        cudaFuncSetAttribute(fp_kernel,
                             cudaFuncAttributeMaxDynamicSharedMemorySize,
                             SMEM_TOTAL);
        once = 1;
    }
    dim3 tb(32, 8);
    dim3 tg(BATCH / 32, F / 32);
    xt_kernel<<<tg, tb>>>(x, b);
    fp_kernel<<<NB, NT, SMEM_TOTAL>>>((float*)d_out, W);
}